// round 12
// baseline (speedup 1.0000x reference)
#include <cuda_runtime.h>
#include <cuda_bf16.h>
#include <cstdint>

// Problem constants (fixed by reference)
#define N_NODES 10000
#define N_EDGES 640000
#define D_IN    128
#define D_HID   256
#define D_OUT   64
#define CAP     192   // per-node edge-slot capacity; deg ~ Poisson(64), P(>192) ~ 0

typedef unsigned long long ull;

// ---------------------------------------------------------------------------
// Scratch (device globals — no allocation allowed)
// ---------------------------------------------------------------------------
__device__ int   g_cursor[N_NODES];
__device__ int2  g_edge[N_NODES * CAP];     // {src, __float_as_int(w)} per slot
__device__ float g_hN1[N_NODES * D_IN];     // layer-1 aggregated neighbor feats
__device__ float g_x1 [N_NODES * D_HID];    // layer-1 output (post relu)
__device__ float g_yS2[N_NODES * D_OUT];    // x1 @ W2_top (self term)
__device__ float g_y2 [N_NODES * D_OUT];    // x1 @ W2_bot (pre-aggregation)

// ---------------------------------------------------------------------------
// packed f32x2 helpers (FFMA2 path — 2x fp32 FMA rate, PTX-only)
// ---------------------------------------------------------------------------
__device__ __forceinline__ ull pack2(float x) {
    ull r;
    asm("mov.b64 %0, {%1, %1};" : "=l"(r) : "f"(x));
    return r;
}
__device__ __forceinline__ void fma2(ull& d, ull a, ull b) {
    asm("fma.rn.f32x2 %0, %1, %2, %0;" : "+l"(d) : "l"(a), "l"(b));
}
__device__ __forceinline__ float2 unpack2(ull v) {
    float2 f;
    asm("mov.b64 {%0, %1}, %2;" : "=f"(f.x), "=f"(f.y) : "l"(v));
    return f;
}

// ---------------------------------------------------------------------------
// Bucket fill: 4 edges per thread (int4/float4 loads -> MLP=4 atomic chains).
// ---------------------------------------------------------------------------
__global__ void k_fill(const int4* __restrict__ dst4,
                       const int4* __restrict__ src4,
                       const float4* __restrict__ w4) {
    int t = blockIdx.x * blockDim.x + threadIdx.x;
    if (t >= N_EDGES / 4) return;
    int4   d  = __ldg(&dst4[t]);
    int4   s  = __ldg(&src4[t]);
    float4 wv = __ldg(&w4[t]);
    int p;
    p = atomicAdd(&g_cursor[d.x], 1); g_edge[d.x * CAP + p] = make_int2(s.x, __float_as_int(wv.x));
    p = atomicAdd(&g_cursor[d.y], 1); g_edge[d.y * CAP + p] = make_int2(s.y, __float_as_int(wv.y));
    p = atomicAdd(&g_cursor[d.z], 1); g_edge[d.z * CAP + p] = make_int2(s.z, __float_as_int(wv.z));
    p = atomicAdd(&g_cursor[d.w], 1); g_edge[d.w * CAP + p] = make_int2(s.w, __float_as_int(wv.w));
}

// ---------------------------------------------------------------------------
// agg1: one warp per node, lane = float4 slice of D_IN=128 (at L2 roofline).
// ---------------------------------------------------------------------------
__global__ __launch_bounds__(256) void k_agg1(const float* __restrict__ x,
                                              float* __restrict__ out) {
    int gw   = (blockIdx.x * blockDim.x + threadIdx.x) >> 5;
    int lane = threadIdx.x & 31;
    if (gw >= N_NODES) return;

    int deg = g_cursor[gw];
    const int2* ep = &g_edge[(size_t)gw * CAP];

    float4 acc = make_float4(0.f, 0.f, 0.f, 0.f);
    int p = 0;
    for (; p + 1 < deg; p += 2) {
        int4 rec = __ldg((const int4*)(ep + p));          // {s0,w0,s1,w1}
        float w0 = __int_as_float(rec.y);
        float w1 = __int_as_float(rec.w);
        float4 r0 = __ldg((const float4*)(x + (size_t)rec.x * D_IN) + lane);
        float4 r1 = __ldg((const float4*)(x + (size_t)rec.z * D_IN) + lane);
        acc.x = fmaf(r0.x, w0, acc.x); acc.y = fmaf(r0.y, w0, acc.y);
        acc.z = fmaf(r0.z, w0, acc.z); acc.w = fmaf(r0.w, w0, acc.w);
        acc.x = fmaf(r1.x, w1, acc.x); acc.y = fmaf(r1.y, w1, acc.y);
        acc.z = fmaf(r1.z, w1, acc.z); acc.w = fmaf(r1.w, w1, acc.w);
    }
    if (p < deg) {
        int2 cur = __ldg(&ep[p]);
        float we = __int_as_float(cur.y);
        float4 r = __ldg((const float4*)(x + (size_t)cur.x * D_IN) + lane);
        acc.x = fmaf(r.x, we, acc.x); acc.y = fmaf(r.y, we, acc.y);
        acc.z = fmaf(r.z, we, acc.z); acc.w = fmaf(r.w, we, acc.w);
    }
    float inv = (deg > 0) ? (1.0f / (float)deg) : 0.0f;
    acc.x *= inv; acc.y *= inv; acc.z *= inv; acc.w *= inv;
    ((float4*)(out + (size_t)gw * D_IN))[lane] = acc;
}

// ---------------------------------------------------------------------------
// agg2 + fused epilogue: lane = float2 slice of D_OUT=64, 2-edge unroll.
//   out[n] = yS[n] + (sum_e y2[src_e] * w_e)/max(deg,1) + b2
// ---------------------------------------------------------------------------
__global__ __launch_bounds__(256) void k_agg2(const float* __restrict__ y2,
                                              const float* __restrict__ yS,
                                              const float* __restrict__ b2,
                                              float* __restrict__ out) {
    int gw   = (blockIdx.x * blockDim.x + threadIdx.x) >> 5;
    int lane = threadIdx.x & 31;
    if (gw >= N_NODES) return;

    int deg = g_cursor[gw];
    const int2* ep = &g_edge[(size_t)gw * CAP];

    float2 acc = make_float2(0.f, 0.f);
    int p = 0;
    for (; p + 1 < deg; p += 2) {
        int4 rec = __ldg((const int4*)(ep + p));
        float w0 = __int_as_float(rec.y);
        float w1 = __int_as_float(rec.w);
        float2 r0 = __ldg((const float2*)(y2 + (size_t)rec.x * D_OUT) + lane);
        float2 r1 = __ldg((const float2*)(y2 + (size_t)rec.z * D_OUT) + lane);
        acc.x = fmaf(r0.x, w0, acc.x); acc.y = fmaf(r0.y, w0, acc.y);
        acc.x = fmaf(r1.x, w1, acc.x); acc.y = fmaf(r1.y, w1, acc.y);
    }
    if (p < deg) {
        int2 cur = __ldg(&ep[p]);
        float we = __int_as_float(cur.y);
        float2 r = __ldg((const float2*)(y2 + (size_t)cur.x * D_OUT) + lane);
        acc.x = fmaf(r.x, we, acc.x); acc.y = fmaf(r.y, we, acc.y);
    }
    float inv = (deg > 0) ? (1.0f / (float)deg) : 0.0f;
    float2 s  = ((const float2*)(yS + (size_t)gw * D_OUT))[lane];
    float2 bb = ((const float2*)b2)[lane];
    float2 o;
    o.x = fmaf(acc.x, inv, s.x) + bb.x;
    o.y = fmaf(acc.y, inv, s.y) + bb.y;
    ((float2*)(out + (size_t)gw * D_OUT))[lane] = o;
}

// ---------------------------------------------------------------------------
// GEMM microkernel notes (both GEMMs):
//  - A tile stored K-major columns: sA[k][row] (row pairs -> LDS64 operands).
//  - B tile stored as DUPLICATED pairs {b,b} in transposed layout:
//      pos(col) = (col & 3) * 16 + (col >> 2)
//    so the inner loop reads B with ONE conflict-free LDS64 (no pack MOVs).
//  - Inner loop per k: 4 LDS64(A) + 4 LDS64(B) + 16 FFMA2  (~67% FMA issues).
//  - Double-buffered smem, ONE __syncthreads per mainloop iteration.
// ---------------------------------------------------------------------------

// GEMM1 (concat + relu): x1 = relu([h | hN1] @ W1 + b1)
// BM=64 BN=64 BK=16 TM=8 TN=4, 128 threads, grid (4, 157).
__global__ __launch_bounds__(128) void k_gemm1(
        const float* __restrict__ A0,   // h   [M,128]
        const float* __restrict__ A1,   // hN1 [M,128]
        const float* __restrict__ W,    // [256,256]
        const float* __restrict__ bias, // [256]
        float* __restrict__ out,        // [M,256]
        int M) {
    __shared__ float sA[2][16][68];
    __shared__ ull   sBd[2][16][64];
    int tid = threadIdx.x;
    int tx  = tid & 15;    // 0..15  (BN/TN)
    int ty  = tid >> 4;    // 0..7   (BM/TM)
    int rowBase = blockIdx.y * 64;
    int colBase = blockIdx.x * 64;

    ull acc[4][4];   // [row-pair][col]
    #pragma unroll
    for (int i = 0; i < 4; i++)
        #pragma unroll
        for (int j = 0; j < 4; j++) acc[i][j] = 0ULL;

    float4 pa[2], pb[2];

    auto loadTiles = [&](int kt) {
        const float* Asrc = (kt < D_IN) ? A0 : A1;
        int kb = kt & (D_IN - 1);
        #pragma unroll
        for (int t = 0; t < 2; t++) {
            int i  = tid + t * 128;       // 0..255
            int r  = i >> 2;              // 0..63
            int s4 = i & 3;               // k-f4 index
            int gr = rowBase + r;
            pa[t] = (gr < M) ? *(const float4*)(Asrc + (size_t)gr * D_IN + kb + s4 * 4)
                             : make_float4(0.f, 0.f, 0.f, 0.f);
        }
        #pragma unroll
        for (int t = 0; t < 2; t++) {
            int i  = tid + t * 128;       // 0..255
            int r  = i >> 4;              // 0..15
            int c4 = i & 15;              // 0..15
            pb[t] = *(const float4*)(W + (size_t)(kt + r) * D_HID + colBase + c4 * 4);
        }
    };
    auto storeTiles = [&](int b) {
        #pragma unroll
        for (int t = 0; t < 2; t++) {
            int i  = tid + t * 128;
            int r  = i >> 2;
            int s4 = i & 3;
            sA[b][s4 * 4 + 0][r] = pa[t].x;
            sA[b][s4 * 4 + 1][r] = pa[t].y;
            sA[b][s4 * 4 + 2][r] = pa[t].z;
            sA[b][s4 * 4 + 3][r] = pa[t].w;
        }
        #pragma unroll
        for (int t = 0; t < 2; t++) {
            int i  = tid + t * 128;
            int r  = i >> 4;
            int c4 = i & 15;
            // col = c4*4 + m  ->  pos = m*16 + c4
            sBd[b][r][0 * 16 + c4] = pack2(pb[t].x);
            sBd[b][r][1 * 16 + c4] = pack2(pb[t].y);
            sBd[b][r][2 * 16 + c4] = pack2(pb[t].z);
            sBd[b][r][3 * 16 + c4] = pack2(pb[t].w);
        }
    };

    constexpr int NIT = (2 * D_IN) / 16;   // 16
    loadTiles(0);
    storeTiles(0);
    __syncthreads();

    for (int it = 0; it < NIT; it++) {
        int b = it & 1;
        if (it + 1 < NIT) loadTiles((it + 1) * 16);
        #pragma unroll
        for (int k = 0; k < 16; k++) {
            const ull* pA = (const ull*)&sA[b][k][ty * 8];
            ull a2[4];
            #pragma unroll
            for (int i = 0; i < 4; i++) a2[i] = pA[i];
            ull bb[4];
            #pragma unroll
            for (int j = 0; j < 4; j++) bb[j] = sBd[b][k][j * 16 + tx];
            #pragma unroll
            for (int i = 0; i < 4; i++)
                #pragma unroll
                for (int j = 0; j < 4; j++) fma2(acc[i][j], a2[i], bb[j]);
        }
        if (it + 1 < NIT) {
            storeTiles(b ^ 1);
            __syncthreads();
        }
    }

    #pragma unroll
    for (int i = 0; i < 4; i++) {
        int gr0 = rowBase + ty * 8 + 2 * i;
        #pragma unroll
        for (int j = 0; j < 4; j++) {
            int gc = colBase + tx * 4 + j;
            float2 v = unpack2(acc[i][j]);
            float b = bias[gc];
            if (gr0 < M)     out[(size_t)gr0 * D_HID + gc]       = fmaxf(v.x + b, 0.f);
            if (gr0 + 1 < M) out[(size_t)(gr0 + 1) * D_HID + gc] = fmaxf(v.y + b, 0.f);
        }
    }
}

// GEMM2 (N-split): blockIdx.x==0: yS = x1 @ W2[0:256]; ==1: y2 = x1 @ W2[256:512]
// BM=64 BN=64 BK=32 TM=8 TN=4, 128 threads, grid (2, 157).
__global__ __launch_bounds__(128) void k_gemm2(
        const float* __restrict__ A,    // x1 [M,256]
        const float* __restrict__ W2,   // [512,64]
        float* __restrict__ yS,         // [M,64]
        float* __restrict__ y2,         // [M,64]
        int M) {
    __shared__ float sA[2][32][68];
    __shared__ ull   sBd[2][32][64];
    int tid = threadIdx.x;
    int tx  = tid & 15;    // 0..15 (BN/TN)
    int ty  = tid >> 4;    // 0..7  (BM/TM)
    int rowBase = blockIdx.y * 64;
    const float* Wbase = W2 + (size_t)blockIdx.x * D_HID * D_OUT;

    ull acc[4][4];
    #pragma unroll
    for (int i = 0; i < 4; i++)
        #pragma unroll
        for (int j = 0; j < 4; j++) acc[i][j] = 0ULL;

    float4 pa[4], pb[4];

    auto loadTiles = [&](int kt) {
        #pragma unroll
        for (int t = 0; t < 4; t++) {
            int i  = tid + t * 128;      // 0..511
            int r  = i >> 3;             // 0..63
            int s4 = i & 7;              // 0..7
            int gr = rowBase + r;
            pa[t] = (gr < M) ? *(const float4*)(A + (size_t)gr * D_HID + kt + s4 * 4)
                             : make_float4(0.f, 0.f, 0.f, 0.f);
        }
        #pragma unroll
        for (int t = 0; t < 4; t++) {
            int i  = tid + t * 128;      // 0..511
            int r  = i >> 4;             // 0..31
            int c4 = i & 15;             // 0..15
            pb[t] = *(const float4*)(Wbase + (size_t)(kt + r) * D_OUT + c4 * 4);
        }
    };
    auto storeTiles = [&](int b) {
        #pragma unroll
        for (int t = 0; t < 4; t++) {
            int i  = tid + t * 128;
            int r  = i >> 3;
            int s4 = i & 7;
            sA[b][s4 * 4 + 0][r] = pa[t].x;
            sA[b][s4 * 4 + 1][r] = pa[t].y;
            sA[b][s4 * 4 + 2][r] = pa[t].z;
            sA[b][s4 * 4 + 3][r] = pa[t].w;
        }
        #pragma unroll
        for (int t = 0; t < 4; t++) {
            int i  = tid + t * 128;
            int r  = i >> 4;
            int c4 = i & 15;
            sBd[b][r][0 * 16 + c4] = pack2(pb[t].x);
            sBd[b][r][1 * 16 + c4] = pack2(pb[t].y);
            sBd[b][r][2 * 16 + c4] = pack2(pb[t].z);
            sBd[b][r][3 * 16 + c4] = pack2(pb[t].w);
        }
    };

    constexpr int NIT = D_HID / 32;   // 8
    loadTiles(0);
    storeTiles(0);
    __syncthreads();

    for (int it = 0; it < NIT; it++) {
        int b = it & 1;
        if (it + 1 < NIT) loadTiles((it + 1) * 32);
        #pragma unroll
        for (int k = 0; k < 32; k++) {
            const ull* pA = (const ull*)&sA[b][k][ty * 8];
            ull a2[4];
            #pragma unroll
            for (int i = 0; i < 4; i++) a2[i] = pA[i];
            ull bb[4];
            #pragma unroll
            for (int j = 0; j < 4; j++) bb[j] = sBd[b][k][j * 16 + tx];
            #pragma unroll
            for (int i = 0; i < 4; i++)
                #pragma unroll
                for (int j = 0; j < 4; j++) fma2(acc[i][j], a2[i], bb[j]);
        }
        if (it + 1 < NIT) {
            storeTiles(b ^ 1);
            __syncthreads();
        }
    }

    float* outp = (blockIdx.x == 0) ? yS : y2;
    #pragma unroll
    for (int i = 0; i < 4; i++) {
        int gr0 = rowBase + ty * 8 + 2 * i;
        #pragma unroll
        for (int j = 0; j < 4; j++) {
            int gc = tx * 4 + j;
            float2 v = unpack2(acc[i][j]);
            if (gr0 < M)     outp[(size_t)gr0 * D_OUT + gc]       = v.x;
            if (gr0 + 1 < M) outp[(size_t)(gr0 + 1) * D_OUT + gc] = v.y;
        }
    }
}

// ---------------------------------------------------------------------------
// launch
// ---------------------------------------------------------------------------
extern "C" void kernel_launch(void* const* d_in, const int* in_sizes, int n_in,
                              void* d_out, int out_size) {
    const float* h   = (const float*)d_in[0];   // [N, 128]
    const float* w   = (const float*)d_in[1];   // [E, 1]
    const int*   src = (const int*)  d_in[2];   // [E]
    const int*   dst = (const int*)  d_in[3];   // [E]
    const float* W1  = (const float*)d_in[4];   // [256, 256]
    const float* b1  = (const float*)d_in[5];   // [256]
    const float* W2  = (const float*)d_in[6];   // [512, 64]
    const float* b2  = (const float*)d_in[7];   // [64]
    float* out = (float*)d_out;                 // [N, 64]

    float *hN1, *x1, *yS2, *y2;
    int* cursor;
    cudaGetSymbolAddress((void**)&hN1,    g_hN1);
    cudaGetSymbolAddress((void**)&x1,     g_x1);
    cudaGetSymbolAddress((void**)&yS2,    g_yS2);
    cudaGetSymbolAddress((void**)&y2,     g_y2);
    cudaGetSymbolAddress((void**)&cursor, g_cursor);

    // --- bucket build ---
    cudaMemsetAsync(cursor, 0, N_NODES * sizeof(int));
    k_fill<<<(N_EDGES / 4 + 255) / 256, 256>>>(
        (const int4*)dst, (const int4*)src, (const float4*)w);

    const int aggBlocks = (N_NODES * 32 + 255) / 256;  // 1 warp per node
    const int rowT64    = (N_NODES + 63) / 64;         // 157

    // --- Layer 1 ---
    k_agg1<<<aggBlocks, 256>>>(h, hN1);
    {
        dim3 grd(D_HID / 64, rowT64);   // (4, 157)
        k_gemm1<<<grd, 128>>>(h, hN1, W1, b1, x1, N_NODES);
    }

    // --- Layer 2 (re-associated) ---
    {
        dim3 grd(2, rowT64);            // (2, 157)
        k_gemm2<<<grd, 128>>>(x1, W2, yS2, y2, N_NODES);
    }
    k_agg2<<<aggBlocks, 256>>>(y2, yS2, b2, out);
}